// round 6
// baseline (speedup 1.0000x reference)
#include <cuda_runtime.h>

// PV_LSTM on GB300 — round 3: 512-thread gate-split batch-parallel kernel.
// Block owns 16 batch rows. Thread (u, gp): u = tid&255 hidden unit,
// gp = tid>>8 gate pair (0 -> gates i,f ; 1 -> gates g,o).
// Packed fma.rn.f32x2 over 8 row-pairs; weights pre-interleaved so each
// thread does one coalesced LDG.128 per 2 k-values.

typedef unsigned long long u64;

#define HD 256
#define BATCH 16384
#define TB 16      // batch rows per block
#define NP 8       // f32x2 row-pairs
#define THREADS 512

// Scratch (allocation-free rule: __device__ globals).
// d_W2[l][gp<<17 | k2<<10 | u<<2 | c]:
//   c=0: Whh[(2gp+0)*256+u][2k2]   c=1: Whh[(2gp+1)*256+u][2k2]
//   c=2: Whh[(2gp+0)*256+u][2k2+1] c=3: Whh[(2gp+1)*256+u][2k2+1]
// d_Wih2[l][gp<<11 | s<<9 | u<<1 | g'] = Wih[(2gp+g')*256+u][s]
// d_b2[l][gp<<9 | u<<1 | g']          = bih+bhh for gate 2gp+g', unit u
__device__ __align__(16) float d_W2[4][HD * HD * 4];
__device__ __align__(16) float d_Wih2[4][4096];
__device__ __align__(16) float d_b2[4][1024];

struct WPtrs {
    const float* Wih[4];
    const float* Whh[4];
    const float* bih[4];
    const float* bhh[4];
};

struct HeadP {
    const float* fcsW; const float* fcsB;   // fc_speed   [4,256],[4]
    const float* fccW; const float* fccB;   // fc_cross   [2,256],[2]
    const float* embW; const float* embB;   // pos_emb    [4,256],[4]
    float* out;
};

// ---------------- packed / approx helpers ----------------
__device__ __forceinline__ u64 fma2(u64 a, u64 b, u64 c) {
    u64 d;
    asm("fma.rn.f32x2 %0, %1, %2, %3;" : "=l"(d) : "l"(a), "l"(b), "l"(c));
    return d;
}
__device__ __forceinline__ u64 bc2(float x) {
    u64 d;
    asm("mov.b64 %0, {%1, %1};" : "=l"(d) : "f"(x));
    return d;
}
__device__ __forceinline__ float2 up2(u64 v) {
    float2 r;
    asm("mov.b64 {%0, %1}, %2;" : "=f"(r.x), "=f"(r.y) : "l"(v));
    return r;
}
__device__ __forceinline__ float tanha(float x) {
    float y;
    asm("tanh.approx.f32 %0, %1;" : "=f"(y) : "f"(x));
    return y;
}
__device__ __forceinline__ float siga(float x) { return 0.5f * tanha(0.5f * x) + 0.5f; }
__device__ __forceinline__ float sigf(float x) { return 1.0f / (1.0f + __expf(-x)); }

// ---------------- weight prep (one launch) ----------------
__global__ void prep_kernel(WPtrs w) {
    int idx = blockIdx.x * 256 + threadIdx.x;
    const int NW = 4 * HD * HD * 4;   // 1048576
    const int NI = 4 * 4096;          // 16384
    const int NB = 4 * 1024;          // 4096
    if (idx < NW) {
        int l = idx >> 18;
        int rem = idx & 262143;
        int c   = rem & 3;
        int u   = (rem >> 2) & 255;
        int k2  = (rem >> 10) & 127;
        int gp  = rem >> 17;
        int g   = 2 * gp + (c & 1);
        int k   = 2 * k2 + (c >> 1);
        d_W2[l][rem] = w.Whh[l][(g * 256 + u) * 256 + k];
    } else if (idx < NW + NI) {
        int j = idx - NW;
        int l = j >> 12;
        int rem = j & 4095;
        int gpr = rem & 1;
        int u   = (rem >> 1) & 255;
        int s   = (rem >> 9) & 3;
        int gp  = rem >> 11;
        d_Wih2[l][rem] = w.Wih[l][((2 * gp + gpr) * 256 + u) * 4 + s];
    } else if (idx < NW + NI + NB) {
        int j = idx - NW - NI;
        int l = j >> 10;
        int rem = j & 1023;
        int gpr = rem & 1;
        int u   = (rem >> 1) & 255;
        int gp  = rem >> 9;
        int g   = 2 * gp + gpr;
        d_b2[l][rem] = w.bih[l][g * 256 + u] + w.bhh[l][g * 256 + u];
    }
}

// ---------------- one LSTM phase: 16 steps for this block's 16 rows ----------------
// mode: 0 encoder, 1 speed decoder, 2 crossing decoder.
// State (c2, hacc/cacc init/fin) is owned by gp==0 threads only.
__device__ __forceinline__ void run_phase(
    int l, int mode,
    const float* __restrict__ xseq,
    int tid, int b0,
    float* sh_h, float4* sh_go4, float* sh_x, const float* sh_hw,
    const float2* h_init, const float2* c_init,
    float2* h_fin, float2* c_fin,
    const HeadP& hp)
{
    const int u  = tid & 255;
    const int gp = tid >> 8;
    float2 c2[NP];

    if (gp == 0) {
        if (h_init) {
#pragma unroll
            for (int p = 0; p < NP; p++) {
                c2[p] = c_init[p];
                sh_h[u * 16 + 2 * p]     = h_init[p].x;
                sh_h[u * 16 + 2 * p + 1] = h_init[p].y;
            }
        } else {
#pragma unroll
            for (int p = 0; p < NP; p++) {
                c2[p] = make_float2(0.f, 0.f);
                sh_h[u * 16 + 2 * p]     = 0.f;
                sh_h[u * 16 + 2 * p + 1] = 0.f;
            }
        }
    }
    if (mode != 0 && tid < 64) {
        int r = tid >> 2, s = tid & 3;
        sh_x[s * 16 + r] = xseq[(size_t)(b0 + r) * 64 + 60 + s];
    }
    __syncthreads();

    for (int t = 0; t < 16; t++) {
        if (mode == 0) {
            if (tid < 64) {
                int r = tid >> 2, s = tid & 3;
                sh_x[s * 16 + r] = xseq[(size_t)(b0 + r) * 64 + t * 4 + s];
            }
            __syncthreads();
        }

        // ---- gate accumulators: bias + Wih*x (a0 = gate 2gp, a1 = gate 2gp+1) ----
        u64 a0[NP], a1[NP];
        {
            const float2 bb = *(const float2*)&d_b2[l][(gp * 256 + u) * 2];
            u64 b0v = bc2(bb.x), b1v = bc2(bb.y);
#pragma unroll
            for (int p = 0; p < NP; p++) { a0[p] = b0v; a1[p] = b1v; }
#pragma unroll
            for (int s = 0; s < 4; s++) {
                const float2 wv = *(const float2*)&d_Wih2[l][((gp * 4 + s) * 256 + u) * 2];
                u64 w0 = bc2(wv.x), w1 = bc2(wv.y);
                const u64* xp = (const u64*)(sh_x + s * 16);
#pragma unroll
                for (int p = 0; p < NP; p++) {
                    u64 x2 = xp[p];
                    a0[p] = fma2(w0, x2, a0[p]);
                    a1[p] = fma2(w1, x2, a1[p]);
                }
            }
        }

        // ---- main recurrence: + Whh*h ----
        const float* wl = d_W2[l] + (gp << 17);
#pragma unroll 8
        for (int k2 = 0; k2 < 128; k2++) {
            const float4 w = *(const float4*)&wl[((k2 << 8) + u) << 2];
            u64 w0e = bc2(w.x), w1e = bc2(w.y), w0o = bc2(w.z), w1o = bc2(w.w);
            const u64* he = (const u64*)(sh_h + (k2 << 5));
            const u64* ho = he + 8;
#pragma unroll
            for (int p = 0; p < NP; p++) {
                u64 h2 = he[p];
                a0[p] = fma2(w0e, h2, a0[p]);
                a1[p] = fma2(w1e, h2, a1[p]);
            }
#pragma unroll
            for (int p = 0; p < NP; p++) {
                u64 h2 = ho[p];
                a0[p] = fma2(w0o, h2, a0[p]);
                a1[p] = fma2(w1o, h2, a1[p]);
            }
        }

        // ---- gate exchange + cell update ----
        if (gp == 1) {
            // a0 = g-gate raw, a1 = o-gate raw -> send tanh(g), sig(o)
#pragma unroll
            for (int p = 0; p < NP; p++) {
                float2 g = up2(a0[p]), o = up2(a1[p]);
                float4 v;
                v.x = tanha(g.x); v.y = tanha(g.y);
                v.z = siga(o.x);  v.w = siga(o.y);
                sh_go4[u * 8 + ((p + u) & 7)] = v;
            }
        }
        __syncthreads();   // go visible; all old-h reads done
        if (gp == 0) {
#pragma unroll
            for (int p = 0; p < NP; p++) {
                float4 go = sh_go4[u * 8 + ((p + u) & 7)];
                float2 vi = up2(a0[p]), vf = up2(a1[p]);
                c2[p].x = siga(vf.x) * c2[p].x + siga(vi.x) * go.x;
                c2[p].y = siga(vf.y) * c2[p].y + siga(vi.y) * go.y;
                float hx = go.z * tanha(c2[p].x);
                float hy = go.w * tanha(c2[p].y);
                sh_h[u * 16 + 2 * p]     = hx;
                sh_h[u * 16 + 2 * p + 1] = hy;
            }
        }
        __syncthreads();   // new h visible

        // ---- decoder heads ----
        if (mode == 1) {
            if (tid < 64) {
                int r = tid >> 2, s = tid & 3;
                float acc = hp.fcsB[s];
                const float* wr = sh_hw + s * 256;
#pragma unroll 8
                for (int k = 0; k < HD; k++) acc += sh_h[k * 16 + r] * wr[k];
                float v = fminf(fmaxf(acc, -100.f), 100.f);   // hardtanh(100)
                hp.out[(size_t)(b0 + r) * 64 + t * 4 + s] = v;
                sh_x[s * 16 + r] = v;                          // feedback
            }
            __syncthreads();
        } else if (mode == 2) {
            if (tid < 64) {
                int r = tid >> 2, s = tid & 3;
                float acc = hp.embB[s];
                const float* wr = sh_hw + 1536 + s * 256;
#pragma unroll 8
                for (int k = 0; k < HD; k++) acc += sh_h[k * 16 + r] * wr[k];
                sh_x[s * 16 + r] = fmaxf(acc, 0.f);            // relu(emb) feedback
            } else if (tid >= 64 && tid < 80) {
                int r = tid - 64;
                float l0 = hp.fccB[0], l1 = hp.fccB[1];
                const float* w0 = sh_hw + 1024;
                const float* w1 = sh_hw + 1280;
#pragma unroll 8
                for (int k = 0; k < HD; k++) {
                    float hv = sh_h[k * 16 + r];
                    l0 += hv * w0[k];
                    l1 += hv * w1[k];
                }
                l0 = fmaxf(l0, 0.f);
                l1 = fmaxf(l1, 0.f);
                float m = fmaxf(l0, l1);
                float e0 = __expf(l0 - m), e1 = __expf(l1 - m);
                float inv = 1.0f / (e0 + e1);
                size_t base = (size_t)BATCH * 64 + (size_t)(b0 + r) * 32 + (size_t)t * 2;
                hp.out[base]     = e0 * inv;
                hp.out[base + 1] = e1 * inv;
            }
            __syncthreads();
        }
    }

    // accumulate final state (encoders): h0 = hsp + hpo, c0 = csp + cpo
    if (gp == 0 && h_fin) {
#pragma unroll
        for (int p = 0; p < NP; p++) {
            h_fin[p].x += sh_h[u * 16 + 2 * p];
            h_fin[p].y += sh_h[u * 16 + 2 * p + 1];
            c_fin[p].x += c2[p].x;
            c_fin[p].y += c2[p].y;
        }
    }
}

// ---------------- whole network, one launch ----------------
// Dynamic smem layout (floats):
//   [0, 4096)          sh_h   h[k][r]                     16 KB
//   [4096, 12288)      sh_go  float4[2048] (g,o exchange) 32 KB
//   [12288, 12352)     sh_x   x[s][r]
//   [12352, 14912)     sh_hw  fcsW | fccW | embW          10 KB
__global__ void __launch_bounds__(THREADS, 1) pv_main(
    HeadP hp, const float* __restrict__ speed, const float* __restrict__ pos)
{
    extern __shared__ __align__(16) float smem[];
    float*  sh_h   = smem;
    float4* sh_go4 = (float4*)(smem + 4096);
    float*  sh_x   = smem + 12288;
    float*  sh_hw  = smem + 12352;

    const int tid = threadIdx.x;
    const int b0 = blockIdx.x * TB;

    // stage head weights
    for (int i = tid; i < 1024; i += THREADS) sh_hw[i] = hp.fcsW[i];
    for (int i = tid; i < 512;  i += THREADS) sh_hw[1024 + i] = hp.fccW[i];
    for (int i = tid; i < 1024; i += THREADS) sh_hw[1536 + i] = hp.embW[i];

    float2 hacc[NP], cacc[NP];
#pragma unroll
    for (int p = 0; p < NP; p++) {
        hacc[p] = make_float2(0.f, 0.f);
        cacc[p] = make_float2(0.f, 0.f);
    }

    // encoders (accumulate summed final state)
    run_phase(0, 0, speed, tid, b0, sh_h, sh_go4, sh_x, sh_hw, nullptr, nullptr, hacc, cacc, hp);
    run_phase(1, 0, pos,   tid, b0, sh_h, sh_go4, sh_x, sh_hw, nullptr, nullptr, hacc, cacc, hp);
    // decoders (both start from (h0, c0))
    run_phase(2, 1, speed, tid, b0, sh_h, sh_go4, sh_x, sh_hw, hacc, cacc, nullptr, nullptr, hp);
    run_phase(3, 2, pos,   tid, b0, sh_h, sh_go4, sh_x, sh_hw, hacc, cacc, nullptr, nullptr, hp);
}

extern "C" void kernel_launch(void* const* d_in, const int* in_sizes, int n_in,
                              void* d_out, int out_size) {
    (void)in_sizes; (void)n_in; (void)out_size;

    WPtrs w;
    // LSTM order: 0=sp_enc, 1=po_enc, 2=dec_speed, 3=dec_cross
    const int base[4] = {2, 6, 10, 14};
    for (int l = 0; l < 4; l++) {
        w.Wih[l] = (const float*)d_in[base[l] + 0];
        w.Whh[l] = (const float*)d_in[base[l] + 1];
        w.bih[l] = (const float*)d_in[base[l] + 2];
        w.bhh[l] = (const float*)d_in[base[l] + 3];
    }

    HeadP hp;
    hp.fcsW = (const float*)d_in[18];
    hp.fcsB = (const float*)d_in[19];
    hp.fccW = (const float*)d_in[20];
    hp.fccB = (const float*)d_in[21];
    hp.embW = (const float*)d_in[22];
    hp.embB = (const float*)d_in[23];
    hp.out  = (float*)d_out;

    const float* speed = (const float*)d_in[0];
    const float* pos   = (const float*)d_in[1];

    const int SMEM_BYTES = 14912 * 4;   // 59648
    cudaFuncSetAttribute(pv_main, cudaFuncAttributeMaxDynamicSharedMemorySize, SMEM_BYTES);

    // (1048576 + 16384 + 4096) / 256 = 4176 blocks
    prep_kernel<<<4176, 256>>>(w);
    pv_main<<<BATCH / TB, THREADS, SMEM_BYTES>>>(hp, speed, pos);
}

// round 7
// speedup vs baseline: 1.0003x; 1.0003x over previous
#include <cuda_runtime.h>

// PV_LSTM on GB300 — round 3: 512-thread gate-split batch-parallel kernel.
// Block owns 16 batch rows. Thread (u, gp): u = tid&255 hidden unit,
// gp = tid>>8 gate pair (0 -> gates i,f ; 1 -> gates g,o).
// Packed fma.rn.f32x2 over 8 row-pairs; weights pre-interleaved so each
// thread does one coalesced LDG.128 per 2 k-values.

typedef unsigned long long u64;

#define HD 256
#define BATCH 16384
#define TB 16      // batch rows per block
#define NP 8       // f32x2 row-pairs
#define THREADS 512

// Scratch (allocation-free rule: __device__ globals).
// d_W2[l][gp<<17 | k2<<10 | u<<2 | c]:
//   c=0: Whh[(2gp+0)*256+u][2k2]   c=1: Whh[(2gp+1)*256+u][2k2]
//   c=2: Whh[(2gp+0)*256+u][2k2+1] c=3: Whh[(2gp+1)*256+u][2k2+1]
// d_Wih2[l][gp<<11 | s<<9 | u<<1 | g'] = Wih[(2gp+g')*256+u][s]
// d_b2[l][gp<<9 | u<<1 | g']          = bih+bhh for gate 2gp+g', unit u
__device__ __align__(16) float d_W2[4][HD * HD * 4];
__device__ __align__(16) float d_Wih2[4][4096];
__device__ __align__(16) float d_b2[4][1024];

struct WPtrs {
    const float* Wih[4];
    const float* Whh[4];
    const float* bih[4];
    const float* bhh[4];
};

struct HeadP {
    const float* fcsW; const float* fcsB;   // fc_speed   [4,256],[4]
    const float* fccW; const float* fccB;   // fc_cross   [2,256],[2]
    const float* embW; const float* embB;   // pos_emb    [4,256],[4]
    float* out;
};

// ---------------- packed / approx helpers ----------------
__device__ __forceinline__ u64 fma2(u64 a, u64 b, u64 c) {
    u64 d;
    asm("fma.rn.f32x2 %0, %1, %2, %3;" : "=l"(d) : "l"(a), "l"(b), "l"(c));
    return d;
}
__device__ __forceinline__ u64 bc2(float x) {
    u64 d;
    asm("mov.b64 %0, {%1, %1};" : "=l"(d) : "f"(x));
    return d;
}
__device__ __forceinline__ float2 up2(u64 v) {
    float2 r;
    asm("mov.b64 {%0, %1}, %2;" : "=f"(r.x), "=f"(r.y) : "l"(v));
    return r;
}
__device__ __forceinline__ float tanha(float x) {
    float y;
    asm("tanh.approx.f32 %0, %1;" : "=f"(y) : "f"(x));
    return y;
}
__device__ __forceinline__ float siga(float x) { return 0.5f * tanha(0.5f * x) + 0.5f; }
__device__ __forceinline__ float sigf(float x) { return 1.0f / (1.0f + __expf(-x)); }

// ---------------- weight prep (one launch) ----------------
__global__ void prep_kernel(WPtrs w) {
    int idx = blockIdx.x * 256 + threadIdx.x;
    const int NW = 4 * HD * HD * 4;   // 1048576
    const int NI = 4 * 4096;          // 16384
    const int NB = 4 * 1024;          // 4096
    if (idx < NW) {
        int l = idx >> 18;
        int rem = idx & 262143;
        int c   = rem & 3;
        int u   = (rem >> 2) & 255;
        int k2  = (rem >> 10) & 127;
        int gp  = rem >> 17;
        int g   = 2 * gp + (c & 1);
        int k   = 2 * k2 + (c >> 1);
        d_W2[l][rem] = w.Whh[l][(g * 256 + u) * 256 + k];
    } else if (idx < NW + NI) {
        int j = idx - NW;
        int l = j >> 12;
        int rem = j & 4095;
        int gpr = rem & 1;
        int u   = (rem >> 1) & 255;
        int s   = (rem >> 9) & 3;
        int gp  = rem >> 11;
        d_Wih2[l][rem] = w.Wih[l][((2 * gp + gpr) * 256 + u) * 4 + s];
    } else if (idx < NW + NI + NB) {
        int j = idx - NW - NI;
        int l = j >> 10;
        int rem = j & 1023;
        int gpr = rem & 1;
        int u   = (rem >> 1) & 255;
        int gp  = rem >> 9;
        int g   = 2 * gp + gpr;
        d_b2[l][rem] = w.bih[l][g * 256 + u] + w.bhh[l][g * 256 + u];
    }
}

// ---------------- one LSTM phase: 16 steps for this block's 16 rows ----------------
// mode: 0 encoder, 1 speed decoder, 2 crossing decoder.
// State (c2, hacc/cacc init/fin) is owned by gp==0 threads only.
__device__ __forceinline__ void run_phase(
    int l, int mode,
    const float* __restrict__ xseq,
    int tid, int b0,
    float* sh_h, float4* sh_go4, float* sh_x, const float* sh_hw,
    const float2* h_init, const float2* c_init,
    float2* h_fin, float2* c_fin,
    const HeadP& hp)
{
    const int u  = tid & 255;
    const int gp = tid >> 8;
    float2 c2[NP];

    if (gp == 0) {
        if (h_init) {
#pragma unroll
            for (int p = 0; p < NP; p++) {
                c2[p] = c_init[p];
                sh_h[u * 16 + 2 * p]     = h_init[p].x;
                sh_h[u * 16 + 2 * p + 1] = h_init[p].y;
            }
        } else {
#pragma unroll
            for (int p = 0; p < NP; p++) {
                c2[p] = make_float2(0.f, 0.f);
                sh_h[u * 16 + 2 * p]     = 0.f;
                sh_h[u * 16 + 2 * p + 1] = 0.f;
            }
        }
    }
    if (mode != 0 && tid < 64) {
        int r = tid >> 2, s = tid & 3;
        sh_x[s * 16 + r] = xseq[(size_t)(b0 + r) * 64 + 60 + s];
    }
    __syncthreads();

    for (int t = 0; t < 16; t++) {
        if (mode == 0) {
            if (tid < 64) {
                int r = tid >> 2, s = tid & 3;
                sh_x[s * 16 + r] = xseq[(size_t)(b0 + r) * 64 + t * 4 + s];
            }
            __syncthreads();
        }

        // ---- gate accumulators: bias + Wih*x (a0 = gate 2gp, a1 = gate 2gp+1) ----
        u64 a0[NP], a1[NP];
        {
            const float2 bb = *(const float2*)&d_b2[l][(gp * 256 + u) * 2];
            u64 b0v = bc2(bb.x), b1v = bc2(bb.y);
#pragma unroll
            for (int p = 0; p < NP; p++) { a0[p] = b0v; a1[p] = b1v; }
#pragma unroll
            for (int s = 0; s < 4; s++) {
                const float2 wv = *(const float2*)&d_Wih2[l][((gp * 4 + s) * 256 + u) * 2];
                u64 w0 = bc2(wv.x), w1 = bc2(wv.y);
                const u64* xp = (const u64*)(sh_x + s * 16);
#pragma unroll
                for (int p = 0; p < NP; p++) {
                    u64 x2 = xp[p];
                    a0[p] = fma2(w0, x2, a0[p]);
                    a1[p] = fma2(w1, x2, a1[p]);
                }
            }
        }

        // ---- main recurrence: + Whh*h ----
        const float* wl = d_W2[l] + (gp << 17);
#pragma unroll 8
        for (int k2 = 0; k2 < 128; k2++) {
            const float4 w = *(const float4*)&wl[((k2 << 8) + u) << 2];
            u64 w0e = bc2(w.x), w1e = bc2(w.y), w0o = bc2(w.z), w1o = bc2(w.w);
            const u64* he = (const u64*)(sh_h + (k2 << 5));
            const u64* ho = he + 8;
#pragma unroll
            for (int p = 0; p < NP; p++) {
                u64 h2 = he[p];
                a0[p] = fma2(w0e, h2, a0[p]);
                a1[p] = fma2(w1e, h2, a1[p]);
            }
#pragma unroll
            for (int p = 0; p < NP; p++) {
                u64 h2 = ho[p];
                a0[p] = fma2(w0o, h2, a0[p]);
                a1[p] = fma2(w1o, h2, a1[p]);
            }
        }

        // ---- gate exchange + cell update ----
        if (gp == 1) {
            // a0 = g-gate raw, a1 = o-gate raw -> send tanh(g), sig(o)
#pragma unroll
            for (int p = 0; p < NP; p++) {
                float2 g = up2(a0[p]), o = up2(a1[p]);
                float4 v;
                v.x = tanha(g.x); v.y = tanha(g.y);
                v.z = siga(o.x);  v.w = siga(o.y);
                sh_go4[u * 8 + ((p + u) & 7)] = v;
            }
        }
        __syncthreads();   // go visible; all old-h reads done
        if (gp == 0) {
#pragma unroll
            for (int p = 0; p < NP; p++) {
                float4 go = sh_go4[u * 8 + ((p + u) & 7)];
                float2 vi = up2(a0[p]), vf = up2(a1[p]);
                c2[p].x = siga(vf.x) * c2[p].x + siga(vi.x) * go.x;
                c2[p].y = siga(vf.y) * c2[p].y + siga(vi.y) * go.y;
                float hx = go.z * tanha(c2[p].x);
                float hy = go.w * tanha(c2[p].y);
                sh_h[u * 16 + 2 * p]     = hx;
                sh_h[u * 16 + 2 * p + 1] = hy;
            }
        }
        __syncthreads();   // new h visible

        // ---- decoder heads ----
        if (mode == 1) {
            if (tid < 64) {
                int r = tid >> 2, s = tid & 3;
                float acc = hp.fcsB[s];
                const float* wr = sh_hw + s * 256;
#pragma unroll 8
                for (int k = 0; k < HD; k++) acc += sh_h[k * 16 + r] * wr[k];
                float v = fminf(fmaxf(acc, -100.f), 100.f);   // hardtanh(100)
                hp.out[(size_t)(b0 + r) * 64 + t * 4 + s] = v;
                sh_x[s * 16 + r] = v;                          // feedback
            }
            __syncthreads();
        } else if (mode == 2) {
            if (tid < 64) {
                int r = tid >> 2, s = tid & 3;
                float acc = hp.embB[s];
                const float* wr = sh_hw + 1536 + s * 256;
#pragma unroll 8
                for (int k = 0; k < HD; k++) acc += sh_h[k * 16 + r] * wr[k];
                sh_x[s * 16 + r] = fmaxf(acc, 0.f);            // relu(emb) feedback
            } else if (tid >= 64 && tid < 80) {
                int r = tid - 64;
                float l0 = hp.fccB[0], l1 = hp.fccB[1];
                const float* w0 = sh_hw + 1024;
                const float* w1 = sh_hw + 1280;
#pragma unroll 8
                for (int k = 0; k < HD; k++) {
                    float hv = sh_h[k * 16 + r];
                    l0 += hv * w0[k];
                    l1 += hv * w1[k];
                }
                l0 = fmaxf(l0, 0.f);
                l1 = fmaxf(l1, 0.f);
                float m = fmaxf(l0, l1);
                float e0 = __expf(l0 - m), e1 = __expf(l1 - m);
                float inv = 1.0f / (e0 + e1);
                size_t base = (size_t)BATCH * 64 + (size_t)(b0 + r) * 32 + (size_t)t * 2;
                hp.out[base]     = e0 * inv;
                hp.out[base + 1] = e1 * inv;
            }
            __syncthreads();
        }
    }

    // accumulate final state (encoders): h0 = hsp + hpo, c0 = csp + cpo
    if (gp == 0 && h_fin) {
#pragma unroll
        for (int p = 0; p < NP; p++) {
            h_fin[p].x += sh_h[u * 16 + 2 * p];
            h_fin[p].y += sh_h[u * 16 + 2 * p + 1];
            c_fin[p].x += c2[p].x;
            c_fin[p].y += c2[p].y;
        }
    }
}

// ---------------- whole network, one launch ----------------
// Dynamic smem layout (floats):
//   [0, 4096)          sh_h   h[k][r]                     16 KB
//   [4096, 12288)      sh_go  float4[2048] (g,o exchange) 32 KB
//   [12288, 12352)     sh_x   x[s][r]
//   [12352, 14912)     sh_hw  fcsW | fccW | embW          10 KB
__global__ void __launch_bounds__(THREADS, 1) pv_main(
    HeadP hp, const float* __restrict__ speed, const float* __restrict__ pos)
{
    extern __shared__ __align__(16) float smem[];
    float*  sh_h   = smem;
    float4* sh_go4 = (float4*)(smem + 4096);
    float*  sh_x   = smem + 12288;
    float*  sh_hw  = smem + 12352;

    const int tid = threadIdx.x;
    const int b0 = blockIdx.x * TB;

    // stage head weights
    for (int i = tid; i < 1024; i += THREADS) sh_hw[i] = hp.fcsW[i];
    for (int i = tid; i < 512;  i += THREADS) sh_hw[1024 + i] = hp.fccW[i];
    for (int i = tid; i < 1024; i += THREADS) sh_hw[1536 + i] = hp.embW[i];

    float2 hacc[NP], cacc[NP];
#pragma unroll
    for (int p = 0; p < NP; p++) {
        hacc[p] = make_float2(0.f, 0.f);
        cacc[p] = make_float2(0.f, 0.f);
    }

    // encoders (accumulate summed final state)
    run_phase(0, 0, speed, tid, b0, sh_h, sh_go4, sh_x, sh_hw, nullptr, nullptr, hacc, cacc, hp);
    run_phase(1, 0, pos,   tid, b0, sh_h, sh_go4, sh_x, sh_hw, nullptr, nullptr, hacc, cacc, hp);
    // decoders (both start from (h0, c0))
    run_phase(2, 1, speed, tid, b0, sh_h, sh_go4, sh_x, sh_hw, hacc, cacc, nullptr, nullptr, hp);
    run_phase(3, 2, pos,   tid, b0, sh_h, sh_go4, sh_x, sh_hw, hacc, cacc, nullptr, nullptr, hp);
}

extern "C" void kernel_launch(void* const* d_in, const int* in_sizes, int n_in,
                              void* d_out, int out_size) {
    (void)in_sizes; (void)n_in; (void)out_size;

    WPtrs w;
    // LSTM order: 0=sp_enc, 1=po_enc, 2=dec_speed, 3=dec_cross
    const int base[4] = {2, 6, 10, 14};
    for (int l = 0; l < 4; l++) {
        w.Wih[l] = (const float*)d_in[base[l] + 0];
        w.Whh[l] = (const float*)d_in[base[l] + 1];
        w.bih[l] = (const float*)d_in[base[l] + 2];
        w.bhh[l] = (const float*)d_in[base[l] + 3];
    }

    HeadP hp;
    hp.fcsW = (const float*)d_in[18];
    hp.fcsB = (const float*)d_in[19];
    hp.fccW = (const float*)d_in[20];
    hp.fccB = (const float*)d_in[21];
    hp.embW = (const float*)d_in[22];
    hp.embB = (const float*)d_in[23];
    hp.out  = (float*)d_out;

    const float* speed = (const float*)d_in[0];
    const float* pos   = (const float*)d_in[1];

    const int SMEM_BYTES = 14912 * 4;   // 59648
    cudaFuncSetAttribute(pv_main, cudaFuncAttributeMaxDynamicSharedMemorySize, SMEM_BYTES);

    // (1048576 + 16384 + 4096) / 256 = 4176 blocks
    prep_kernel<<<4176, 256>>>(w);
    pv_main<<<BATCH / TB, THREADS, SMEM_BYTES>>>(hp, speed, pos);
}

// round 8
// speedup vs baseline: 1.0013x; 1.0010x over previous
#include <cuda_runtime.h>

// PV_LSTM on GB300 — round 3: 512-thread gate-split batch-parallel kernel.
// Block owns 16 batch rows. Thread (u, gp): u = tid&255 hidden unit,
// gp = tid>>8 gate pair (0 -> gates i,f ; 1 -> gates g,o).
// Packed fma.rn.f32x2 over 8 row-pairs; weights pre-interleaved so each
// thread does one coalesced LDG.128 per 2 k-values.

typedef unsigned long long u64;

#define HD 256
#define BATCH 16384
#define TB 16      // batch rows per block
#define NP 8       // f32x2 row-pairs
#define THREADS 512

// Scratch (allocation-free rule: __device__ globals).
// d_W2[l][gp<<17 | k2<<10 | u<<2 | c]:
//   c=0: Whh[(2gp+0)*256+u][2k2]   c=1: Whh[(2gp+1)*256+u][2k2]
//   c=2: Whh[(2gp+0)*256+u][2k2+1] c=3: Whh[(2gp+1)*256+u][2k2+1]
// d_Wih2[l][gp<<11 | s<<9 | u<<1 | g'] = Wih[(2gp+g')*256+u][s]
// d_b2[l][gp<<9 | u<<1 | g']          = bih+bhh for gate 2gp+g', unit u
__device__ __align__(16) float d_W2[4][HD * HD * 4];
__device__ __align__(16) float d_Wih2[4][4096];
__device__ __align__(16) float d_b2[4][1024];

struct WPtrs {
    const float* Wih[4];
    const float* Whh[4];
    const float* bih[4];
    const float* bhh[4];
};

struct HeadP {
    const float* fcsW; const float* fcsB;   // fc_speed   [4,256],[4]
    const float* fccW; const float* fccB;   // fc_cross   [2,256],[2]
    const float* embW; const float* embB;   // pos_emb    [4,256],[4]
    float* out;
};

// ---------------- packed / approx helpers ----------------
__device__ __forceinline__ u64 fma2(u64 a, u64 b, u64 c) {
    u64 d;
    asm("fma.rn.f32x2 %0, %1, %2, %3;" : "=l"(d) : "l"(a), "l"(b), "l"(c));
    return d;
}
__device__ __forceinline__ u64 bc2(float x) {
    u64 d;
    asm("mov.b64 %0, {%1, %1};" : "=l"(d) : "f"(x));
    return d;
}
__device__ __forceinline__ float2 up2(u64 v) {
    float2 r;
    asm("mov.b64 {%0, %1}, %2;" : "=f"(r.x), "=f"(r.y) : "l"(v));
    return r;
}
__device__ __forceinline__ float tanha(float x) {
    float y;
    asm("tanh.approx.f32 %0, %1;" : "=f"(y) : "f"(x));
    return y;
}
__device__ __forceinline__ float siga(float x) { return 0.5f * tanha(0.5f * x) + 0.5f; }
__device__ __forceinline__ float sigf(float x) { return 1.0f / (1.0f + __expf(-x)); }

// ---------------- weight prep (one launch) ----------------
__global__ void prep_kernel(WPtrs w) {
    int idx = blockIdx.x * 256 + threadIdx.x;
    const int NW = 4 * HD * HD * 4;   // 1048576
    const int NI = 4 * 4096;          // 16384
    const int NB = 4 * 1024;          // 4096
    if (idx < NW) {
        int l = idx >> 18;
        int rem = idx & 262143;
        int c   = rem & 3;
        int u   = (rem >> 2) & 255;
        int k2  = (rem >> 10) & 127;
        int gp  = rem >> 17;
        int g   = 2 * gp + (c & 1);
        int k   = 2 * k2 + (c >> 1);
        d_W2[l][rem] = w.Whh[l][(g * 256 + u) * 256 + k];
    } else if (idx < NW + NI) {
        int j = idx - NW;
        int l = j >> 12;
        int rem = j & 4095;
        int gpr = rem & 1;
        int u   = (rem >> 1) & 255;
        int s   = (rem >> 9) & 3;
        int gp  = rem >> 11;
        d_Wih2[l][rem] = w.Wih[l][((2 * gp + gpr) * 256 + u) * 4 + s];
    } else if (idx < NW + NI + NB) {
        int j = idx - NW - NI;
        int l = j >> 10;
        int rem = j & 1023;
        int gpr = rem & 1;
        int u   = (rem >> 1) & 255;
        int gp  = rem >> 9;
        int g   = 2 * gp + gpr;
        d_b2[l][rem] = w.bih[l][g * 256 + u] + w.bhh[l][g * 256 + u];
    }
}

// ---------------- one LSTM phase: 16 steps for this block's 16 rows ----------------
// mode: 0 encoder, 1 speed decoder, 2 crossing decoder.
// State (c2, hacc/cacc init/fin) is owned by gp==0 threads only.
__device__ __forceinline__ void run_phase(
    int l, int mode,
    const float* __restrict__ xseq,
    int tid, int b0,
    float* sh_h, float4* sh_go4, float* sh_x, const float* sh_hw,
    const float2* h_init, const float2* c_init,
    float2* h_fin, float2* c_fin,
    const HeadP& hp)
{
    const int u  = tid & 255;
    const int gp = tid >> 8;
    float2 c2[NP];

    if (gp == 0) {
        if (h_init) {
#pragma unroll
            for (int p = 0; p < NP; p++) {
                c2[p] = c_init[p];
                sh_h[u * 16 + 2 * p]     = h_init[p].x;
                sh_h[u * 16 + 2 * p + 1] = h_init[p].y;
            }
        } else {
#pragma unroll
            for (int p = 0; p < NP; p++) {
                c2[p] = make_float2(0.f, 0.f);
                sh_h[u * 16 + 2 * p]     = 0.f;
                sh_h[u * 16 + 2 * p + 1] = 0.f;
            }
        }
    }
    if (mode != 0 && tid < 64) {
        int r = tid >> 2, s = tid & 3;
        sh_x[s * 16 + r] = xseq[(size_t)(b0 + r) * 64 + 60 + s];
    }
    __syncthreads();

    for (int t = 0; t < 16; t++) {
        if (mode == 0) {
            if (tid < 64) {
                int r = tid >> 2, s = tid & 3;
                sh_x[s * 16 + r] = xseq[(size_t)(b0 + r) * 64 + t * 4 + s];
            }
            __syncthreads();
        }

        // ---- gate accumulators: bias + Wih*x (a0 = gate 2gp, a1 = gate 2gp+1) ----
        u64 a0[NP], a1[NP];
        {
            const float2 bb = *(const float2*)&d_b2[l][(gp * 256 + u) * 2];
            u64 b0v = bc2(bb.x), b1v = bc2(bb.y);
#pragma unroll
            for (int p = 0; p < NP; p++) { a0[p] = b0v; a1[p] = b1v; }
#pragma unroll
            for (int s = 0; s < 4; s++) {
                const float2 wv = *(const float2*)&d_Wih2[l][((gp * 4 + s) * 256 + u) * 2];
                u64 w0 = bc2(wv.x), w1 = bc2(wv.y);
                const u64* xp = (const u64*)(sh_x + s * 16);
#pragma unroll
                for (int p = 0; p < NP; p++) {
                    u64 x2 = xp[p];
                    a0[p] = fma2(w0, x2, a0[p]);
                    a1[p] = fma2(w1, x2, a1[p]);
                }
            }
        }

        // ---- main recurrence: + Whh*h ----
        const float* wl = d_W2[l] + (gp << 17);
#pragma unroll 8
        for (int k2 = 0; k2 < 128; k2++) {
            const float4 w = *(const float4*)&wl[((k2 << 8) + u) << 2];
            u64 w0e = bc2(w.x), w1e = bc2(w.y), w0o = bc2(w.z), w1o = bc2(w.w);
            const u64* he = (const u64*)(sh_h + (k2 << 5));
            const u64* ho = he + 8;
#pragma unroll
            for (int p = 0; p < NP; p++) {
                u64 h2 = he[p];
                a0[p] = fma2(w0e, h2, a0[p]);
                a1[p] = fma2(w1e, h2, a1[p]);
            }
#pragma unroll
            for (int p = 0; p < NP; p++) {
                u64 h2 = ho[p];
                a0[p] = fma2(w0o, h2, a0[p]);
                a1[p] = fma2(w1o, h2, a1[p]);
            }
        }

        // ---- gate exchange + cell update ----
        if (gp == 1) {
            // a0 = g-gate raw, a1 = o-gate raw -> send tanh(g), sig(o)
#pragma unroll
            for (int p = 0; p < NP; p++) {
                float2 g = up2(a0[p]), o = up2(a1[p]);
                float4 v;
                v.x = tanha(g.x); v.y = tanha(g.y);
                v.z = siga(o.x);  v.w = siga(o.y);
                sh_go4[u * 8 + ((p + u) & 7)] = v;
            }
        }
        __syncthreads();   // go visible; all old-h reads done
        if (gp == 0) {
#pragma unroll
            for (int p = 0; p < NP; p++) {
                float4 go = sh_go4[u * 8 + ((p + u) & 7)];
                float2 vi = up2(a0[p]), vf = up2(a1[p]);
                c2[p].x = siga(vf.x) * c2[p].x + siga(vi.x) * go.x;
                c2[p].y = siga(vf.y) * c2[p].y + siga(vi.y) * go.y;
                float hx = go.z * tanha(c2[p].x);
                float hy = go.w * tanha(c2[p].y);
                sh_h[u * 16 + 2 * p]     = hx;
                sh_h[u * 16 + 2 * p + 1] = hy;
            }
        }
        __syncthreads();   // new h visible

        // ---- decoder heads ----
        if (mode == 1) {
            if (tid < 64) {
                int r = tid >> 2, s = tid & 3;
                float acc = hp.fcsB[s];
                const float* wr = sh_hw + s * 256;
#pragma unroll 8
                for (int k = 0; k < HD; k++) acc += sh_h[k * 16 + r] * wr[k];
                float v = fminf(fmaxf(acc, -100.f), 100.f);   // hardtanh(100)
                hp.out[(size_t)(b0 + r) * 64 + t * 4 + s] = v;
                sh_x[s * 16 + r] = v;                          // feedback
            }
            __syncthreads();
        } else if (mode == 2) {
            if (tid < 64) {
                int r = tid >> 2, s = tid & 3;
                float acc = hp.embB[s];
                const float* wr = sh_hw + 1536 + s * 256;
#pragma unroll 8
                for (int k = 0; k < HD; k++) acc += sh_h[k * 16 + r] * wr[k];
                sh_x[s * 16 + r] = fmaxf(acc, 0.f);            // relu(emb) feedback
            } else if (tid >= 64 && tid < 80) {
                int r = tid - 64;
                float l0 = hp.fccB[0], l1 = hp.fccB[1];
                const float* w0 = sh_hw + 1024;
                const float* w1 = sh_hw + 1280;
#pragma unroll 8
                for (int k = 0; k < HD; k++) {
                    float hv = sh_h[k * 16 + r];
                    l0 += hv * w0[k];
                    l1 += hv * w1[k];
                }
                l0 = fmaxf(l0, 0.f);
                l1 = fmaxf(l1, 0.f);
                float m = fmaxf(l0, l1);
                float e0 = __expf(l0 - m), e1 = __expf(l1 - m);
                float inv = 1.0f / (e0 + e1);
                size_t base = (size_t)BATCH * 64 + (size_t)(b0 + r) * 32 + (size_t)t * 2;
                hp.out[base]     = e0 * inv;
                hp.out[base + 1] = e1 * inv;
            }
            __syncthreads();
        }
    }

    // accumulate final state (encoders): h0 = hsp + hpo, c0 = csp + cpo
    if (gp == 0 && h_fin) {
#pragma unroll
        for (int p = 0; p < NP; p++) {
            h_fin[p].x += sh_h[u * 16 + 2 * p];
            h_fin[p].y += sh_h[u * 16 + 2 * p + 1];
            c_fin[p].x += c2[p].x;
            c_fin[p].y += c2[p].y;
        }
    }
}

// ---------------- whole network, one launch ----------------
// Dynamic smem layout (floats):
//   [0, 4096)          sh_h   h[k][r]                     16 KB
//   [4096, 12288)      sh_go  float4[2048] (g,o exchange) 32 KB
//   [12288, 12352)     sh_x   x[s][r]
//   [12352, 14912)     sh_hw  fcsW | fccW | embW          10 KB
__global__ void __launch_bounds__(THREADS, 1) pv_main(
    HeadP hp, const float* __restrict__ speed, const float* __restrict__ pos)
{
    extern __shared__ __align__(16) float smem[];
    float*  sh_h   = smem;
    float4* sh_go4 = (float4*)(smem + 4096);
    float*  sh_x   = smem + 12288;
    float*  sh_hw  = smem + 12352;

    const int tid = threadIdx.x;
    const int b0 = blockIdx.x * TB;

    // stage head weights
    for (int i = tid; i < 1024; i += THREADS) sh_hw[i] = hp.fcsW[i];
    for (int i = tid; i < 512;  i += THREADS) sh_hw[1024 + i] = hp.fccW[i];
    for (int i = tid; i < 1024; i += THREADS) sh_hw[1536 + i] = hp.embW[i];

    float2 hacc[NP], cacc[NP];
#pragma unroll
    for (int p = 0; p < NP; p++) {
        hacc[p] = make_float2(0.f, 0.f);
        cacc[p] = make_float2(0.f, 0.f);
    }

    // encoders (accumulate summed final state)
    run_phase(0, 0, speed, tid, b0, sh_h, sh_go4, sh_x, sh_hw, nullptr, nullptr, hacc, cacc, hp);
    run_phase(1, 0, pos,   tid, b0, sh_h, sh_go4, sh_x, sh_hw, nullptr, nullptr, hacc, cacc, hp);
    // decoders (both start from (h0, c0))
    run_phase(2, 1, speed, tid, b0, sh_h, sh_go4, sh_x, sh_hw, hacc, cacc, nullptr, nullptr, hp);
    run_phase(3, 2, pos,   tid, b0, sh_h, sh_go4, sh_x, sh_hw, hacc, cacc, nullptr, nullptr, hp);
}

extern "C" void kernel_launch(void* const* d_in, const int* in_sizes, int n_in,
                              void* d_out, int out_size) {
    (void)in_sizes; (void)n_in; (void)out_size;

    WPtrs w;
    // LSTM order: 0=sp_enc, 1=po_enc, 2=dec_speed, 3=dec_cross
    const int base[4] = {2, 6, 10, 14};
    for (int l = 0; l < 4; l++) {
        w.Wih[l] = (const float*)d_in[base[l] + 0];
        w.Whh[l] = (const float*)d_in[base[l] + 1];
        w.bih[l] = (const float*)d_in[base[l] + 2];
        w.bhh[l] = (const float*)d_in[base[l] + 3];
    }

    HeadP hp;
    hp.fcsW = (const float*)d_in[18];
    hp.fcsB = (const float*)d_in[19];
    hp.fccW = (const float*)d_in[20];
    hp.fccB = (const float*)d_in[21];
    hp.embW = (const float*)d_in[22];
    hp.embB = (const float*)d_in[23];
    hp.out  = (float*)d_out;

    const float* speed = (const float*)d_in[0];
    const float* pos   = (const float*)d_in[1];

    const int SMEM_BYTES = 14912 * 4;   // 59648
    cudaFuncSetAttribute(pv_main, cudaFuncAttributeMaxDynamicSharedMemorySize, SMEM_BYTES);

    // (1048576 + 16384 + 4096) / 256 = 4176 blocks
    prep_kernel<<<4176, 256>>>(w);
    pv_main<<<BATCH / TB, THREADS, SMEM_BYTES>>>(hp, speed, pos);
}